// round 13
// baseline (speedup 1.0000x reference)
#include <cuda_runtime.h>
#include <cstdint>

// out[b,p,d] = (sum_h hs[b,p,h] * W[prop[b,p], h, d] + bias[prop[b,p], d]) * mask[b,p]
// B=512, P=128 -> 65536 rows, H=512, D=2. One warp per row.
// Best-measured configuration (R7, 29.15us) + W evict_last:
//   hs row (2KB, DRAM stream) cp.async.cg with L2::evict_first (never pollutes L2)
//   W  row (4KB, gather)      cp.async.cg with L2::evict_last  (41MB table stays
//                             L2-resident within and across graph replays)
// Single commit/wait per warp, conflict-free LDS consume, warp shfl reduce.

#define NROWS 65536
#define HDIM 512
#define WARPS_PER_BLK 4

__global__ __launch_bounds__(128) void adapter_kernel(
    const float* __restrict__ hs,          // [65536, 512]
    const int* __restrict__ props,         // [65536] int32
    const float* __restrict__ mask,        // [65536]
    const float* __restrict__ W,           // [10000, 512, 2]
    const float* __restrict__ bias,        // [10000, 2]
    float* __restrict__ out)               // [65536, 2]
{
    __shared__ float4 hbuf[WARPS_PER_BLK][128];   // 2KB per warp
    __shared__ float4 wbuf[WARPS_PER_BLK][256];   // 4KB per warp

    const int warp = threadIdx.x >> 5;
    const int lane = threadIdx.x & 31;
    const int row = blockIdx.x * WARPS_PER_BLK + warp;

    const int p = __ldg(&props[row]);

    const float4* __restrict__ h4 = reinterpret_cast<const float4*>(hs + (size_t)row * HDIM);
    const float4* __restrict__ w4 = reinterpret_cast<const float4*>(W + (size_t)p * (HDIM * 2));

    // L2 policies: hs = evict_first (pure stream), W = evict_last (resident table).
    uint64_t pol_first, pol_last;
    asm volatile("createpolicy.fractional.L2::evict_first.b64 %0, 1.0;" : "=l"(pol_first));
    asm volatile("createpolicy.fractional.L2::evict_last.b64 %0, 1.0;" : "=l"(pol_last));

    // hs: 4 x 16B per lane, coalesced, streamed.
    #pragma unroll
    for (int i = 0; i < 4; i++) {
        uint32_t dst = (uint32_t)__cvta_generic_to_shared(&hbuf[warp][i * 32 + lane]);
        asm volatile("cp.async.cg.shared.global.L2::cache_hint [%0], [%1], 16, %2;"
                     :: "r"(dst), "l"(h4 + i * 32 + lane), "l"(pol_first) : "memory");
    }
    // W: 8 x 16B per lane, coalesced, kept L2-resident.
    #pragma unroll
    for (int i = 0; i < 8; i++) {
        uint32_t dst = (uint32_t)__cvta_generic_to_shared(&wbuf[warp][i * 32 + lane]);
        asm volatile("cp.async.cg.shared.global.L2::cache_hint [%0], [%1], 16, %2;"
                     :: "r"(dst), "l"(w4 + i * 32 + lane), "l"(pol_last) : "memory");
    }
    asm volatile("cp.async.commit_group;" ::: "memory");
    asm volatile("cp.async.wait_group 0;" ::: "memory");
    __syncwarp();   // consume reads cross-lane copies

    // Consume: W linear (conflict-free LDS.128), hs as float2 (stride-8B,
    // conflict-free LDS.64). wbuf[idx] = (W[h,0],W[h,1],W[h+1,0],W[h+1,1]), h=2*idx.
    const float2* __restrict__ h2 = reinterpret_cast<const float2*>(hbuf[warp]);

    float acc0 = 0.f, acc1 = 0.f;
    #pragma unroll
    for (int j = 0; j < 8; j++) {
        const int idx = j * 32 + lane;
        const float4 wv = wbuf[warp][idx];
        const float2 hh = h2[idx];
        acc0 = fmaf(hh.x, wv.x, acc0);
        acc1 = fmaf(hh.x, wv.y, acc1);
        acc0 = fmaf(hh.y, wv.z, acc0);
        acc1 = fmaf(hh.y, wv.w, acc1);
    }

    // Warp tree reduction
    #pragma unroll
    for (int off = 16; off > 0; off >>= 1) {
        acc0 += __shfl_xor_sync(0xFFFFFFFFu, acc0, off);
        acc1 += __shfl_xor_sync(0xFFFFFFFFu, acc1, off);
    }

    if (lane == 0) {
        const float m = mask[row];
        const float b0 = __ldg(&bias[p * 2 + 0]);
        const float b1 = __ldg(&bias[p * 2 + 1]);
        float2 r;
        r.x = (acc0 + b0) * m;
        r.y = (acc1 + b1) * m;
        __stcs(reinterpret_cast<float2*>(out) + row, r);
    }
}

extern "C" void kernel_launch(void* const* d_in, const int* in_sizes, int n_in,
                              void* d_out, int out_size)
{
    const float* hs    = (const float*)d_in[0];
    const int*   props = (const int*)d_in[1];
    const float* mask  = (const float*)d_in[2];
    const float* W     = (const float*)d_in[3];
    const float* bias  = (const float*)d_in[4];
    float*       out   = (float*)d_out;

    const int threads = 32 * WARPS_PER_BLK;
    const int blocks = NROWS / WARPS_PER_BLK;
    adapter_kernel<<<blocks, threads>>>(hs, props, mask, W, bias, out);
}

// round 14
// speedup vs baseline: 1.0132x; 1.0132x over previous
#include <cuda_runtime.h>
#include <cstdint>

// out[b,p,d] = (sum_h hs[b,p,h] * W[prop[b,p], h, d] + bias[prop[b,p], d]) * mask[b,p]
// B=512, P=128 -> 65536 rows, H=512, D=2. One warp per row.
// CHAMPION (R7, 29.15us): both operand rows staged via cp.async.cg (no register
// residency during flight):
//   hs row (2KB, DRAM stream) with L2::evict_first policy -> keeps the 41MB W
//   table L2-resident; W row (4KB, L2-resident gather) default policy.
// Single commit/wait, then conflict-free LDS consume + warp shfl reduce.
// Session conclusion: timed regime is LTS-service bound (~396MB @ ~13.5TB/s);
// all occupancy/MLP/staging/locality variants pinned at 29.1-29.4us.

#define NROWS 65536
#define HDIM 512
#define WARPS_PER_BLK 4

__global__ __launch_bounds__(128) void adapter_kernel(
    const float* __restrict__ hs,          // [65536, 512]
    const int* __restrict__ props,         // [65536] int32
    const float* __restrict__ mask,        // [65536]
    const float* __restrict__ W,           // [10000, 512, 2]
    const float* __restrict__ bias,        // [10000, 2]
    float* __restrict__ out)               // [65536, 2]
{
    __shared__ float4 hbuf[WARPS_PER_BLK][128];   // 2KB per warp
    __shared__ float4 wbuf[WARPS_PER_BLK][256];   // 4KB per warp

    const int warp = threadIdx.x >> 5;
    const int lane = threadIdx.x & 31;
    const int row = blockIdx.x * WARPS_PER_BLK + warp;

    const int p = __ldg(&props[row]);

    const float4* __restrict__ h4 = reinterpret_cast<const float4*>(hs + (size_t)row * HDIM);
    const float4* __restrict__ w4 = reinterpret_cast<const float4*>(W + (size_t)p * (HDIM * 2));

    // Evict-first policy for the hs stream (protects W residency in L2).
    uint64_t pol;
    asm volatile("createpolicy.fractional.L2::evict_first.b64 %0, 1.0;" : "=l"(pol));

    // hs: 4 x 16B per lane, coalesced, streamed.
    #pragma unroll
    for (int i = 0; i < 4; i++) {
        uint32_t dst = (uint32_t)__cvta_generic_to_shared(&hbuf[warp][i * 32 + lane]);
        asm volatile("cp.async.cg.shared.global.L2::cache_hint [%0], [%1], 16, %2;"
                     :: "r"(dst), "l"(h4 + i * 32 + lane), "l"(pol) : "memory");
    }
    // W: 8 x 16B per lane, coalesced, default (cached) policy.
    #pragma unroll
    for (int i = 0; i < 8; i++) {
        uint32_t dst = (uint32_t)__cvta_generic_to_shared(&wbuf[warp][i * 32 + lane]);
        asm volatile("cp.async.cg.shared.global [%0], [%1], 16;"
                     :: "r"(dst), "l"(w4 + i * 32 + lane) : "memory");
    }
    asm volatile("cp.async.commit_group;" ::: "memory");
    asm volatile("cp.async.wait_group 0;" ::: "memory");
    __syncwarp();   // consume reads cross-lane copies

    // Consume: W linear (conflict-free LDS.128), hs as float2 (stride-8B,
    // conflict-free LDS.64). wbuf[idx] = (W[h,0],W[h,1],W[h+1,0],W[h+1,1]), h=2*idx.
    const float2* __restrict__ h2 = reinterpret_cast<const float2*>(hbuf[warp]);

    float acc0 = 0.f, acc1 = 0.f;
    #pragma unroll
    for (int j = 0; j < 8; j++) {
        const int idx = j * 32 + lane;
        const float4 wv = wbuf[warp][idx];
        const float2 hh = h2[idx];
        acc0 = fmaf(hh.x, wv.x, acc0);
        acc1 = fmaf(hh.x, wv.y, acc1);
        acc0 = fmaf(hh.y, wv.z, acc0);
        acc1 = fmaf(hh.y, wv.w, acc1);
    }

    // Warp tree reduction
    #pragma unroll
    for (int off = 16; off > 0; off >>= 1) {
        acc0 += __shfl_xor_sync(0xFFFFFFFFu, acc0, off);
        acc1 += __shfl_xor_sync(0xFFFFFFFFu, acc1, off);
    }

    if (lane == 0) {
        const float m = mask[row];
        const float b0 = __ldg(&bias[p * 2 + 0]);
        const float b1 = __ldg(&bias[p * 2 + 1]);
        float2 r;
        r.x = (acc0 + b0) * m;
        r.y = (acc1 + b1) * m;
        __stcs(reinterpret_cast<float2*>(out) + row, r);
    }
}

extern "C" void kernel_launch(void* const* d_in, const int* in_sizes, int n_in,
                              void* d_out, int out_size)
{
    const float* hs    = (const float*)d_in[0];
    const int*   props = (const int*)d_in[1];
    const float* mask  = (const float*)d_in[2];
    const float* W     = (const float*)d_in[3];
    const float* bias  = (const float*)d_in[4];
    float*       out   = (float*)d_out;

    const int threads = 32 * WARPS_PER_BLK;
    const int blocks = NROWS / WARPS_PER_BLK;
    adapter_kernel<<<blocks, threads>>>(hs, props, mask, W, bias, out);
}